// round 11
// baseline (speedup 1.0000x reference)
#include <cuda_runtime.h>
#include <cuda_bf16.h>
#include <cuda_fp16.h>
#include <cstdint>

// Problem constants
#define NN 10000
#define DD 128
#define NDSZ (NN * DD)

// Scratch (device globals; no allocations)
__device__ float g_qkvs[2 * NDSZ];        // Q (fp32), S (fp32)
__device__ uint4 g_kv[NN * 32];           // packed fp16 K|V: per node 32 x 16B
__device__ float g_h[NDSZ];               // hidden after layer 0
__device__ int   g_rowptr[NN + 1];

// ===========================================================================
// row_ptr: edges sorted by src; rowptr[i] = first index with src[e] >= i
// ===========================================================================
__global__ void build_rowptr_kernel(const int* __restrict__ src, int E) {
    int i = blockIdx.x * blockDim.x + threadIdx.x;
    if (i > NN) return;
    int lo = 0, hi = E;
    while (lo < hi) {
        int mid = (lo + hi) >> 1;
        if (src[mid] < i) lo = mid + 1; else hi = mid;
    }
    g_rowptr[i] = lo;
}

// ===========================================================================
// TF32 helpers (portable mma.sync PTX — compiles under compute_103)
// ===========================================================================
__device__ __forceinline__ uint32_t f2tf32(float x) {
    uint32_t r;
    asm("cvt.rna.tf32.f32 %0, %1;" : "=r"(r) : "f"(x));
    return r;
}

__device__ __forceinline__ void mma_tf32(float* c, const uint32_t* a, const uint32_t* b) {
    asm volatile(
        "mma.sync.aligned.m16n8k8.row.col.f32.tf32.tf32.f32 "
        "{%0,%1,%2,%3}, {%4,%5,%6,%7}, {%8,%9}, {%0,%1,%2,%3};"
        : "+f"(c[0]), "+f"(c[1]), "+f"(c[2]), "+f"(c[3])
        : "r"(a[0]), "r"(a[1]), "r"(a[2]), "r"(a[3]),
          "r"(b[0]), "r"(b[1]));
}

// ===========================================================================
// Projection GEMM via TF32x3 with FRAGMENT-MAJOR smem (all LDS.128).
// CTA tile 64x128, 4 warps (2M x 2N), warp tile 32x64. grid (157, 4).
// A fragment layout: [m16(4)][k8(2)][lane(32)][reg(4)] -> uint4 per lane.
// B fragment layout: [k(16)][p=n&7(8)][q=n>>3(16)], row stride 132 words
//   (132 mod 32 = 4 -> conflict-free LDS.128 phases).
// Q,S -> fp32 g_qkvs; K,V -> packed fp16 g_kv.
// ===========================================================================
#define BROW 132

__global__ __launch_bounds__(128, 4)
void gemm_tf32_kernel(const float* __restrict__ xin,
                      const float* __restrict__ Wq, const float* __restrict__ Wk,
                      const float* __restrict__ Wv, const float* __restrict__ Ws,
                      const float* __restrict__ bq, const float* __restrict__ bk,
                      const float* __restrict__ bv, const float* __restrict__ bs,
                      int layer, int use_gh) {
    __shared__ uint32_t sAh[1024];        // 4 m16-blocks x 2 k8 x 32 lanes x 4
    __shared__ uint32_t sAl[1024];
    __shared__ uint32_t sBh[16 * BROW];   // 16 k-rows x (8p x 16q + pad)
    __shared__ uint32_t sBl[16 * BROW];

    const int tid  = threadIdx.x;
    const int wid  = tid >> 5;
    const int lane = tid & 31;
    const int g    = lane >> 2;    // 0..7
    const int tg   = lane & 3;     // 0..3
    const int warpM = wid & 1;     // 0..1 (32 rows each)
    const int warpN = wid >> 1;    // 0..1 (64 cols each)

    const int rowbase = blockIdx.x * 64;
    const int mtx = blockIdx.y;

    const float* A = use_gh ? g_h : xin;
    const float* W = (mtx == 0 ? Wq : mtx == 1 ? Wk : mtx == 2 ? Wv : Ws)
                     + (size_t)layer * DD * DD;
    const float* bias = (mtx == 0 ? bq : mtx == 1 ? bk : mtx == 2 ? bv : bs)
                        + layer * DD;

    float acc[2][8][4];
    #pragma unroll
    for (int mi = 0; mi < 2; ++mi)
        #pragma unroll
        for (int ni = 0; ni < 8; ++ni)
            #pragma unroll
            for (int r = 0; r < 4; ++r) acc[mi][ni][r] = 0.f;

    for (int k0 = 0; k0 < DD; k0 += 16) {
        // ---- stage A chunk 64x16 into fragment-major (2 float4/thread) ----
        #pragma unroll
        for (int r = 0; r < 2; ++r) {
            int f = tid + r * 128;
            int row = f >> 2;          // 0..63
            int c4  = f & 3;           // k group of 4
            int m = rowbase + row;
            float4 v = make_float4(0.f, 0.f, 0.f, 0.f);
            if (m < NN) v = *(const float4*)&A[(size_t)m * DD + k0 + c4 * 4];
            // word = (m16*2+k8)*128 + (row&7)*16 + j*4 + reg
            int b0 = ((row >> 4) * 2 + (c4 >> 1)) * 128 + (row & 7) * 16
                   + ((row >> 3) & 1) + (c4 & 1) * 2;
            const float* vp = (const float*)&v;
            #pragma unroll
            for (int j = 0; j < 4; ++j) {
                uint32_t h = f2tf32(vp[j]);
                sAh[b0 + j * 4] = h;
                sAl[b0 + j * 4] = f2tf32(vp[j] - __uint_as_float(h));
            }
        }
        // ---- stage B chunk 16x128 into fragment-major (4 float4/thread) ----
        #pragma unroll
        for (int r = 0; r < 4; ++r) {
            int f = tid + r * 128;
            int kr = f >> 5;           // 0..15
            int c4 = f & 31;           // n group of 4
            float4 v = *(const float4*)&W[(size_t)(k0 + kr) * DD + c4 * 4];
            // word = kr*BROW + p*16 + q ; p=(c4&1)*4+j, q=c4>>1
            int wb = kr * BROW + (c4 & 1) * 64 + (c4 >> 1);
            const float* vp = (const float*)&v;
            #pragma unroll
            for (int j = 0; j < 4; ++j) {
                uint32_t h = f2tf32(vp[j]);
                sBh[wb + j * 16] = h;
                sBl[wb + j * 16] = f2tf32(vp[j] - __uint_as_float(h));
            }
        }
        __syncthreads();

        #pragma unroll
        for (int ks = 0; ks < 2; ++ks) {
            uint4 ah[2], al[2];
            #pragma unroll
            for (int mi = 0; mi < 2; ++mi) {
                int idx = (((warpM * 2 + mi) * 2) + ks) * 128 + lane * 4;
                ah[mi] = *(const uint4*)&sAh[idx];
                al[mi] = *(const uint4*)&sAl[idx];
            }
            int kr0 = ks * 8 + tg;
            int b0 = kr0 * BROW + g * 16 + warpN * 8;
            int b1 = (kr0 + 4) * BROW + g * 16 + warpN * 8;
            uint32_t bh0[8], bh1[8], bl0[8], bl1[8];
            *(uint4*)&bh0[0] = *(const uint4*)&sBh[b0];
            *(uint4*)&bh0[4] = *(const uint4*)&sBh[b0 + 4];
            *(uint4*)&bh1[0] = *(const uint4*)&sBh[b1];
            *(uint4*)&bh1[4] = *(const uint4*)&sBh[b1 + 4];
            *(uint4*)&bl0[0] = *(const uint4*)&sBl[b0];
            *(uint4*)&bl0[4] = *(const uint4*)&sBl[b0 + 4];
            *(uint4*)&bl1[0] = *(const uint4*)&sBl[b1];
            *(uint4*)&bl1[4] = *(const uint4*)&sBl[b1 + 4];

            #pragma unroll
            for (int ni = 0; ni < 8; ++ni) {
                uint32_t bhf[2] = { bh0[ni], bh1[ni] };
                uint32_t blf[2] = { bl0[ni], bl1[ni] };
                #pragma unroll
                for (int mi = 0; mi < 2; ++mi) {
                    mma_tf32(acc[mi][ni], (const uint32_t*)&ah[mi], bhf);
                    mma_tf32(acc[mi][ni], (const uint32_t*)&al[mi], bhf);
                    mma_tf32(acc[mi][ni], (const uint32_t*)&ah[mi], blf);
                }
            }
        }
        __syncthreads();
    }

    // ---- epilogue: bias + store ----
    #pragma unroll
    for (int mi = 0; mi < 2; ++mi) {
        int m0 = rowbase + warpM * 32 + mi * 16 + g;
        int m1 = m0 + 8;
        #pragma unroll
        for (int ni = 0; ni < 8; ++ni) {
            int n = warpN * 64 + ni * 8 + tg * 2;
            float2 b2 = *(const float2*)&bias[n];
            float2 o0 = make_float2(acc[mi][ni][0] + b2.x, acc[mi][ni][1] + b2.y);
            float2 o1 = make_float2(acc[mi][ni][2] + b2.x, acc[mi][ni][3] + b2.y);
            if (mtx == 0 || mtx == 3) {
                float* outb = g_qkvs + (mtx == 0 ? 0 : NDSZ);
                if (m0 < NN) *(float2*)&outb[(size_t)m0 * DD + n] = o0;
                if (m1 < NN) *(float2*)&outb[(size_t)m1 * DD + n] = o1;
            } else {
                // packed fp16 K|V: node row 512B; 16B section per 4 dims;
                // K at +0, V at +8; within-section offset (n&3)*2
                size_t sect = (size_t)(n >> 2) * 16 + (mtx == 2 ? 8 : 0) + (n & 3) * 2;
                if (m0 < NN)
                    *(__half2*)((char*)g_kv + (size_t)m0 * 512 + sect) = __floats2half2_rn(o0.x, o0.y);
                if (m1 < NN)
                    *(__half2*)((char*)g_kv + (size_t)m1 * 512 + sect) = __floats2half2_rn(o1.x, o1.y);
            }
        }
    }
}

// ===========================================================================
// Attention: one warp per destination node; dual-stream online softmax;
// ONE LDG.128 per edge per lane (packed fp16 K|V). Q/S/h fp32.
// ===========================================================================
__device__ __forceinline__ void unpack_kv(uint4 kv, float4& k4, float4& v4) {
    float2 a = __half22float2(*(__half2*)&kv.x);
    float2 b = __half22float2(*(__half2*)&kv.y);
    float2 c = __half22float2(*(__half2*)&kv.z);
    float2 d = __half22float2(*(__half2*)&kv.w);
    k4 = make_float4(a.x, a.y, b.x, b.y);
    v4 = make_float4(c.x, c.y, d.x, d.y);
}

__global__ __launch_bounds__(256)
void attn_kernel(const float* __restrict__ xin,
                 const int* __restrict__ nbr,
                 float* __restrict__ outp, int mode) {
    int gwarp = (blockIdx.x * blockDim.x + threadIdx.x) >> 5;
    if (gwarp >= NN) return;
    const int lane = threadIdx.x & 31;
    const int i = gwarp;

    const float* Q = g_qkvs;
    const float* S = g_qkvs + NDSZ;
    const float* h = mode ? g_h : xin;

    float4 q4 = *(const float4*)&Q[(size_t)i * DD + lane * 4];
    q4.x *= 0.25f; q4.y *= 0.25f; q4.z *= 0.25f; q4.w *= 0.25f;

    float m0 = -1e30f, z0 = 0.f, m1 = -1e30f, z1 = 0.f;
    float4 a0 = make_float4(0.f, 0.f, 0.f, 0.f);
    float4 a1 = make_float4(0.f, 0.f, 0.f, 0.f);

    const int e0 = g_rowptr[i];
    const int e1 = g_rowptr[i + 1];

    int e = e0;
    int jA = nbr[e0];
    int jB = (e0 + 1 < e1) ? nbr[e0 + 1] : 0;

    while (e + 1 < e1) {
        int jA2 = (e + 2 < e1) ? nbr[e + 2] : 0;
        int jB2 = (e + 3 < e1) ? nbr[e + 3] : 0;

        uint4 kvA = g_kv[(size_t)jA * 32 + lane];
        uint4 kvB = g_kv[(size_t)jB * 32 + lane];
        float4 kA, vA, kB, vB;
        unpack_kv(kvA, kA, vA);
        unpack_kv(kvB, kB, vB);

        float dA = q4.x * kA.x + q4.y * kA.y + q4.z * kA.z + q4.w * kA.w;
        float dB = q4.x * kB.x + q4.y * kB.y + q4.z * kB.z + q4.w * kB.w;
        dA += __shfl_xor_sync(0xFFFFFFFFu, dA, 1);
        dB += __shfl_xor_sync(0xFFFFFFFFu, dB, 1);
        dA += __shfl_xor_sync(0xFFFFFFFFu, dA, 2);
        dB += __shfl_xor_sync(0xFFFFFFFFu, dB, 2);

        float nm0 = fmaxf(m0, dA);
        float s0 = __expf(m0 - nm0);
        float p0 = __expf(dA - nm0);
        z0 = z0 * s0 + p0;
        a0.x = a0.x * s0 + p0 * vA.x;
        a0.y = a0.y * s0 + p0 * vA.y;
        a0.z = a0.z * s0 + p0 * vA.z;
        a0.w = a0.w * s0 + p0 * vA.w;
        m0 = nm0;

        float nm1 = fmaxf(m1, dB);
        float s1 = __expf(m1 - nm1);
        float p1 = __expf(dB - nm1);
        z1 = z1 * s1 + p1;
        a1.x = a1.x * s1 + p1 * vB.x;
        a1.y = a1.y * s1 + p1 * vB.y;
        a1.z = a1.z * s1 + p1 * vB.z;
        a1.w = a1.w * s1 + p1 * vB.w;
        m1 = nm1;

        jA = jA2; jB = jB2; e += 2;
    }
    if (e < e1) {   // leftover single edge -> stream 0
        uint4 kvA = g_kv[(size_t)jA * 32 + lane];
        float4 kA, vA;
        unpack_kv(kvA, kA, vA);
        float dA = q4.x * kA.x + q4.y * kA.y + q4.z * kA.z + q4.w * kA.w;
        dA += __shfl_xor_sync(0xFFFFFFFFu, dA, 1);
        dA += __shfl_xor_sync(0xFFFFFFFFu, dA, 2);
        float nm0 = fmaxf(m0, dA);
        float s0 = __expf(m0 - nm0);
        float p0 = __expf(dA - nm0);
        z0 = z0 * s0 + p0;
        a0.x = a0.x * s0 + p0 * vA.x;
        a0.y = a0.y * s0 + p0 * vA.y;
        a0.z = a0.z * s0 + p0 * vA.z;
        a0.w = a0.w * s0 + p0 * vA.w;
        m0 = nm0;
    }

    // merge streams
    float M = fmaxf(m0, m1);
    float s0 = __expf(m0 - M);
    float s1 = __expf(m1 - M);
    float z = z0 * s0 + z1 * s1;
    float inv = 1.f / z;
    float4 acc;
    acc.x = a0.x * s0 + a1.x * s1;
    acc.y = a0.y * s0 + a1.y * s1;
    acc.z = a0.z * s0 + a1.z * s1;
    acc.w = a0.w * s0 + a1.w * s1;

    float4 h4 = *(const float4*)&h[(size_t)i * DD + lane * 4];
    float4 s4 = *(const float4*)&S[(size_t)i * DD + lane * 4];
    float4 o;
    o.x = acc.x * inv + h4.x + s4.x;
    o.y = acc.y * inv + h4.y + s4.y;
    o.z = acc.z * inv + h4.z + s4.z;
    o.w = acc.w * inv + h4.w + s4.w;

    if (mode == 0) {
        o.x = fmaxf(o.x, 0.f); o.y = fmaxf(o.y, 0.f);
        o.z = fmaxf(o.z, 0.f); o.w = fmaxf(o.w, 0.f);
        *(float4*)&g_h[(size_t)i * DD + lane * 4] = o;
    } else {
        *(float4*)&outp[(size_t)i * DD + lane * 4] = o;
    }
}

// ===========================================================================
// Launch — only kernel launches.
// Inputs: 0=x 1=Wq 2=bq 3=Wk 4=bk 5=Wv 6=bv 7=Ws 8=bs 9=attn_window[2,E] int32
// ===========================================================================
extern "C" void kernel_launch(void* const* d_in, const int* in_sizes, int n_in,
                              void* d_out, int out_size) {
    const float* x  = (const float*)d_in[0];
    const float* Wq = (const float*)d_in[1];
    const float* bq = (const float*)d_in[2];
    const float* Wk = (const float*)d_in[3];
    const float* bk = (const float*)d_in[4];
    const float* Wv = (const float*)d_in[5];
    const float* bv = (const float*)d_in[6];
    const float* Ws = (const float*)d_in[7];
    const float* bs = (const float*)d_in[8];
    const int*   aw = (const int*)d_in[9];
    const int E = in_sizes[9] / 2;
    const int* src = aw;
    const int* dst = aw + E;

    build_rowptr_kernel<<<(NN + 256) / 256, 256>>>(src, E);

    dim3 ggrid((NN + 63) / 64, 4);
    dim3 agrid((NN * 32 + 255) / 256);

    // Layer 0
    gemm_tf32_kernel<<<ggrid, 128>>>(x, Wq, Wk, Wv, Ws, bq, bk, bv, bs, 0, 0);
    attn_kernel<<<agrid, 256>>>(x, dst, nullptr, 0);

    // Layer 1
    gemm_tf32_kernel<<<ggrid, 128>>>(x, Wq, Wk, Wv, Ws, bq, bk, bv, bs, 1, 1);
    attn_kernel<<<agrid, 256>>>(nullptr, dst, (float*)d_out, 1);
}

// round 12
// speedup vs baseline: 1.0550x; 1.0550x over previous
#include <cuda_runtime.h>
#include <cuda_bf16.h>
#include <cuda_fp16.h>
#include <cstdint>

// Problem constants
#define NN 10000
#define DD 128
#define NDSZ (NN * DD)

// Scratch (device globals; no allocations)
__device__ float g_qkvs[2 * NDSZ];        // Q (fp32), S (fp32)
__device__ uint4 g_kv[NN * 32];           // packed fp16 K|V: per node 32 x 16B
__device__ float g_h[NDSZ];               // hidden after layer 0
__device__ int   g_rowptr[NN + 1];

// ===========================================================================
// row_ptr: edges sorted by src; rowptr[i] = first index with src[e] >= i
// ===========================================================================
__global__ void build_rowptr_kernel(const int* __restrict__ src, int E) {
    int i = blockIdx.x * blockDim.x + threadIdx.x;
    if (i > NN) return;
    int lo = 0, hi = E;
    while (lo < hi) {
        int mid = (lo + hi) >> 1;
        if (src[mid] < i) lo = mid + 1; else hi = mid;
    }
    g_rowptr[i] = lo;
}

// ===========================================================================
// TF32 helpers (portable mma.sync PTX — compiles under compute_103)
// ===========================================================================
__device__ __forceinline__ uint32_t f2tf32(float x) {
    uint32_t r;
    asm("cvt.rna.tf32.f32 %0, %1;" : "=r"(r) : "f"(x));
    return r;
}

__device__ __forceinline__ void mma_tf32(float* c, const uint32_t* a, const uint32_t* b) {
    asm volatile(
        "mma.sync.aligned.m16n8k8.row.col.f32.tf32.tf32.f32 "
        "{%0,%1,%2,%3}, {%4,%5,%6,%7}, {%8,%9}, {%0,%1,%2,%3};"
        : "+f"(c[0]), "+f"(c[1]), "+f"(c[2]), "+f"(c[3])
        : "r"(a[0]), "r"(a[1]), "r"(a[2]), "r"(a[3]),
          "r"(b[0]), "r"(b[1]));
}

// ===========================================================================
// Projection GEMM via TF32x3 (R10-proven version): out = A @ W + bias.
// CTA tile 64x128, 8 warps (4M x 2N), warp tile 16x64. grid (157, 4).
// Q,S -> fp32 g_qkvs; K,V -> packed fp16 g_kv.
// ===========================================================================
#define ASTRIDE 20
#define BSTRIDE 136

__global__ __launch_bounds__(256)
void gemm_tf32_kernel(const float* __restrict__ xin,
                      const float* __restrict__ Wq, const float* __restrict__ Wk,
                      const float* __restrict__ Wv, const float* __restrict__ Ws,
                      const float* __restrict__ bq, const float* __restrict__ bk,
                      const float* __restrict__ bv, const float* __restrict__ bs,
                      int layer, int use_gh) {
    __shared__ uint32_t sAh[64 * ASTRIDE];
    __shared__ uint32_t sAl[64 * ASTRIDE];
    __shared__ uint32_t sBh[16 * BSTRIDE];
    __shared__ uint32_t sBl[16 * BSTRIDE];

    const int tid  = threadIdx.x;
    const int wid  = tid >> 5;
    const int lane = tid & 31;
    const int g    = lane >> 2;    // 0..7
    const int tg   = lane & 3;     // 0..3
    const int warpM = wid & 3;     // 0..3 (16 rows each)
    const int warpN = wid >> 2;    // 0..1 (64 cols each)

    const int rowbase = blockIdx.x * 64;
    const int mtx = blockIdx.y;

    const float* A = use_gh ? g_h : xin;
    const float* W = (mtx == 0 ? Wq : mtx == 1 ? Wk : mtx == 2 ? Wv : Ws)
                     + (size_t)layer * DD * DD;
    const float* bias = (mtx == 0 ? bq : mtx == 1 ? bk : mtx == 2 ? bv : bs)
                        + layer * DD;

    float acc[8][4];
    #pragma unroll
    for (int ni = 0; ni < 8; ++ni)
        #pragma unroll
        for (int r = 0; r < 4; ++r) acc[ni][r] = 0.f;

    for (int k0 = 0; k0 < DD; k0 += 16) {
        // ---- stage A chunk 64x16 (1 float4 per thread) ----
        {
            int row = tid >> 2;
            int c4  = tid & 3;
            int m = rowbase + row;
            float4 v = make_float4(0.f, 0.f, 0.f, 0.f);
            if (m < NN) v = *(const float4*)&A[(size_t)m * DD + k0 + c4 * 4];
            uint4 h, l;
            h.x = f2tf32(v.x); l.x = f2tf32(v.x - __uint_as_float(h.x));
            h.y = f2tf32(v.y); l.y = f2tf32(v.y - __uint_as_float(h.y));
            h.z = f2tf32(v.z); l.z = f2tf32(v.z - __uint_as_float(h.z));
            h.w = f2tf32(v.w); l.w = f2tf32(v.w - __uint_as_float(h.w));
            *(uint4*)&sAh[row * ASTRIDE + c4 * 4] = h;
            *(uint4*)&sAl[row * ASTRIDE + c4 * 4] = l;
        }
        // ---- stage B chunk 16x128 (2 float4 per thread) ----
        #pragma unroll
        for (int r = 0; r < 2; ++r) {
            int f = tid + r * 256;
            int kr = f >> 5;
            int c4 = f & 31;
            float4 v = *(const float4*)&W[(size_t)(k0 + kr) * DD + c4 * 4];
            uint4 h, l;
            h.x = f2tf32(v.x); l.x = f2tf32(v.x - __uint_as_float(h.x));
            h.y = f2tf32(v.y); l.y = f2tf32(v.y - __uint_as_float(h.y));
            h.z = f2tf32(v.z); l.z = f2tf32(v.z - __uint_as_float(h.z));
            h.w = f2tf32(v.w); l.w = f2tf32(v.w - __uint_as_float(h.w));
            *(uint4*)&sBh[kr * BSTRIDE + c4 * 4] = h;
            *(uint4*)&sBl[kr * BSTRIDE + c4 * 4] = l;
        }
        __syncthreads();

        #pragma unroll
        for (int ks = 0; ks < 2; ++ks) {
            int ko = ks * 8;
            uint32_t ah[4], al[4];
            int r0 = (warpM * 16 + g) * ASTRIDE;
            ah[0] = sAh[r0 + ko + tg];
            ah[1] = sAh[r0 + 8 * ASTRIDE + ko + tg];
            ah[2] = sAh[r0 + ko + tg + 4];
            ah[3] = sAh[r0 + 8 * ASTRIDE + ko + tg + 4];
            al[0] = sAl[r0 + ko + tg];
            al[1] = sAl[r0 + 8 * ASTRIDE + ko + tg];
            al[2] = sAl[r0 + ko + tg + 4];
            al[3] = sAl[r0 + 8 * ASTRIDE + ko + tg + 4];
            #pragma unroll
            for (int ni = 0; ni < 8; ++ni) {
                int n0 = warpN * 64 + ni * 8 + g;
                uint32_t bh[2], bl[2];
                bh[0] = sBh[(ko + tg) * BSTRIDE + n0];
                bh[1] = sBh[(ko + tg + 4) * BSTRIDE + n0];
                bl[0] = sBl[(ko + tg) * BSTRIDE + n0];
                bl[1] = sBl[(ko + tg + 4) * BSTRIDE + n0];
                mma_tf32(acc[ni], ah, bh);
                mma_tf32(acc[ni], al, bh);
                mma_tf32(acc[ni], ah, bl);
            }
        }
        __syncthreads();
    }

    // ---- epilogue ----
    int m0 = rowbase + warpM * 16 + g;
    int m1 = m0 + 8;
    #pragma unroll
    for (int ni = 0; ni < 8; ++ni) {
        int n = warpN * 64 + ni * 8 + tg * 2;
        float2 b2 = *(const float2*)&bias[n];
        float2 o0 = make_float2(acc[ni][0] + b2.x, acc[ni][1] + b2.y);
        float2 o1 = make_float2(acc[ni][2] + b2.x, acc[ni][3] + b2.y);
        if (mtx == 0 || mtx == 3) {
            float* outb = g_qkvs + (mtx == 0 ? 0 : NDSZ);
            if (m0 < NN) *(float2*)&outb[(size_t)m0 * DD + n] = o0;
            if (m1 < NN) *(float2*)&outb[(size_t)m1 * DD + n] = o1;
        } else {
            // packed fp16 K|V: node row 512B; 16B section per 4 dims;
            // K at +0, V at +8; within-section offset (n&3)*2
            size_t sect = (size_t)(n >> 2) * 16 + (mtx == 2 ? 8 : 0) + (n & 3) * 2;
            if (m0 < NN)
                *(__half2*)((char*)g_kv + (size_t)m0 * 512 + sect) = __floats2half2_rn(o0.x, o0.y);
            if (m1 < NN)
                *(__half2*)((char*)g_kv + (size_t)m1 * 512 + sect) = __floats2half2_rn(o1.x, o1.y);
        }
    }
}

// ===========================================================================
// Attention: one warp per destination node; FOUR independent online-softmax
// streams (edges e..e+3 per iteration) — 4 KV LDG.128 in flight per warp.
// ONE LDG.128 per edge per lane (packed fp16 K|V). Q/S/h fp32.
// ===========================================================================
__device__ __forceinline__ void unpack_kv(uint4 kv, float4& k4, float4& v4) {
    float2 a = __half22float2(*(__half2*)&kv.x);
    float2 b = __half22float2(*(__half2*)&kv.y);
    float2 c = __half22float2(*(__half2*)&kv.z);
    float2 d = __half22float2(*(__half2*)&kv.w);
    k4 = make_float4(a.x, a.y, b.x, b.y);
    v4 = make_float4(c.x, c.y, d.x, d.y);
}

struct SmaxStream {
    float m, z;
    float4 a;
};

__device__ __forceinline__ void smax_update(SmaxStream& s, float d, const float4& v) {
    float nm = fmaxf(s.m, d);
    float sc = __expf(s.m - nm);
    float p  = __expf(d - nm);
    s.z = s.z * sc + p;
    s.a.x = s.a.x * sc + p * v.x;
    s.a.y = s.a.y * sc + p * v.y;
    s.a.z = s.a.z * sc + p * v.z;
    s.a.w = s.a.w * sc + p * v.w;
    s.m = nm;
}

// merge s1 into s0 (flash combine; handles empty streams via exp(-inf)=0)
__device__ __forceinline__ void smax_merge(SmaxStream& s0, const SmaxStream& s1) {
    float M = fmaxf(s0.m, s1.m);
    float c0 = __expf(s0.m - M);
    float c1 = __expf(s1.m - M);
    s0.z = s0.z * c0 + s1.z * c1;
    s0.a.x = s0.a.x * c0 + s1.a.x * c1;
    s0.a.y = s0.a.y * c0 + s1.a.y * c1;
    s0.a.z = s0.a.z * c0 + s1.a.z * c1;
    s0.a.w = s0.a.w * c0 + s1.a.w * c1;
    s0.m = M;
}

__global__ __launch_bounds__(256)
void attn_kernel(const float* __restrict__ xin,
                 const int* __restrict__ nbr,
                 float* __restrict__ outp, int mode) {
    int gwarp = (blockIdx.x * blockDim.x + threadIdx.x) >> 5;
    if (gwarp >= NN) return;
    const int lane = threadIdx.x & 31;
    const int i = gwarp;

    const float* Q = g_qkvs;
    const float* S = g_qkvs + NDSZ;
    const float* h = mode ? g_h : xin;

    float4 q4 = *(const float4*)&Q[(size_t)i * DD + lane * 4];
    q4.x *= 0.25f; q4.y *= 0.25f; q4.z *= 0.25f; q4.w *= 0.25f;

    SmaxStream st[4];
    #pragma unroll
    for (int s = 0; s < 4; ++s) {
        st[s].m = -1e30f; st[s].z = 0.f;
        st[s].a = make_float4(0.f, 0.f, 0.f, 0.f);
    }

    const int e0 = g_rowptr[i];
    const int e1 = g_rowptr[i + 1];

    int e = e0;
    // main 4-edge loop
    while (e + 3 < e1) {
        int j0 = nbr[e];
        int j1 = nbr[e + 1];
        int j2 = nbr[e + 2];
        int j3 = nbr[e + 3];
        uint4 kv0 = g_kv[(size_t)j0 * 32 + lane];
        uint4 kv1 = g_kv[(size_t)j1 * 32 + lane];
        uint4 kv2 = g_kv[(size_t)j2 * 32 + lane];
        uint4 kv3 = g_kv[(size_t)j3 * 32 + lane];

        float4 k0, v0, k1, v1, k2, v2, k3, v3;
        unpack_kv(kv0, k0, v0);
        unpack_kv(kv1, k1, v1);
        unpack_kv(kv2, k2, v2);
        unpack_kv(kv3, k3, v3);

        float d0 = q4.x * k0.x + q4.y * k0.y + q4.z * k0.z + q4.w * k0.w;
        float d1 = q4.x * k1.x + q4.y * k1.y + q4.z * k1.z + q4.w * k1.w;
        float d2 = q4.x * k2.x + q4.y * k2.y + q4.z * k2.z + q4.w * k2.w;
        float d3 = q4.x * k3.x + q4.y * k3.y + q4.z * k3.z + q4.w * k3.w;
        d0 += __shfl_xor_sync(0xFFFFFFFFu, d0, 1);
        d1 += __shfl_xor_sync(0xFFFFFFFFu, d1, 1);
        d2 += __shfl_xor_sync(0xFFFFFFFFu, d2, 1);
        d3 += __shfl_xor_sync(0xFFFFFFFFu, d3, 1);
        d0 += __shfl_xor_sync(0xFFFFFFFFu, d0, 2);
        d1 += __shfl_xor_sync(0xFFFFFFFFu, d1, 2);
        d2 += __shfl_xor_sync(0xFFFFFFFFu, d2, 2);
        d3 += __shfl_xor_sync(0xFFFFFFFFu, d3, 2);

        smax_update(st[0], d0, v0);
        smax_update(st[1], d1, v1);
        smax_update(st[2], d2, v2);
        smax_update(st[3], d3, v3);
        e += 4;
    }
    // remainder -> stream 0
    while (e < e1) {
        int j0 = nbr[e];
        uint4 kv0 = g_kv[(size_t)j0 * 32 + lane];
        float4 k0, v0;
        unpack_kv(kv0, k0, v0);
        float d0 = q4.x * k0.x + q4.y * k0.y + q4.z * k0.z + q4.w * k0.w;
        d0 += __shfl_xor_sync(0xFFFFFFFFu, d0, 1);
        d0 += __shfl_xor_sync(0xFFFFFFFFu, d0, 2);
        smax_update(st[0], d0, v0);
        ++e;
    }

    // merge 4 streams pairwise
    smax_merge(st[0], st[1]);
    smax_merge(st[2], st[3]);
    smax_merge(st[0], st[2]);

    float inv = 1.f / st[0].z;
    float4 h4 = *(const float4*)&h[(size_t)i * DD + lane * 4];
    float4 s4 = *(const float4*)&S[(size_t)i * DD + lane * 4];
    float4 o;
    o.x = st[0].a.x * inv + h4.x + s4.x;
    o.y = st[0].a.y * inv + h4.y + s4.y;
    o.z = st[0].a.z * inv + h4.z + s4.z;
    o.w = st[0].a.w * inv + h4.w + s4.w;

    if (mode == 0) {
        o.x = fmaxf(o.x, 0.f); o.y = fmaxf(o.y, 0.f);
        o.z = fmaxf(o.z, 0.f); o.w = fmaxf(o.w, 0.f);
        *(float4*)&g_h[(size_t)i * DD + lane * 4] = o;
    } else {
        *(float4*)&outp[(size_t)i * DD + lane * 4] = o;
    }
}

// ===========================================================================
// Launch — only kernel launches.
// Inputs: 0=x 1=Wq 2=bq 3=Wk 4=bk 5=Wv 6=bv 7=Ws 8=bs 9=attn_window[2,E] int32
// ===========================================================================
extern "C" void kernel_launch(void* const* d_in, const int* in_sizes, int n_in,
                              void* d_out, int out_size) {
    const float* x  = (const float*)d_in[0];
    const float* Wq = (const float*)d_in[1];
    const float* bq = (const float*)d_in[2];
    const float* Wk = (const float*)d_in[3];
    const float* bk = (const float*)d_in[4];
    const float* Wv = (const float*)d_in[5];
    const float* bv = (const float*)d_in[6];
    const float* Ws = (const float*)d_in[7];
    const float* bs = (const float*)d_in[8];
    const int*   aw = (const int*)d_in[9];
    const int E = in_sizes[9] / 2;
    const int* src = aw;
    const int* dst = aw + E;

    build_rowptr_kernel<<<(NN + 256) / 256, 256>>>(src, E);

    dim3 ggrid((NN + 63) / 64, 4);
    dim3 agrid((NN * 32 + 255) / 256);

    // Layer 0
    gemm_tf32_kernel<<<ggrid, 256>>>(x, Wq, Wk, Wv, Ws, bq, bk, bv, bs, 0, 0);
    attn_kernel<<<agrid, 256>>>(x, dst, nullptr, 0);

    // Layer 1
    gemm_tf32_kernel<<<ggrid, 256>>>(x, Wq, Wk, Wv, Ws, bq, bk, bv, bs, 1, 1);
    attn_kernel<<<agrid, 256>>>(nullptr, dst, (float*)d_out, 1);
}

// round 13
// speedup vs baseline: 1.1299x; 1.0710x over previous
#include <cuda_runtime.h>
#include <cuda_bf16.h>
#include <cuda_fp16.h>
#include <cstdint>

// Problem constants
#define NN 10000
#define DD 128
#define NDSZ (NN * DD)

// Scratch (device globals; no allocations)
__device__ float g_qkvs[2 * NDSZ];        // Q (fp32), S (fp32)
__device__ uint4 g_kv[NN * 32];           // per node 512B: [K 128 fp16 | V 128 fp16]
__device__ float g_h[NDSZ];               // hidden after layer 0
__device__ int   g_rowptr[NN + 1];

// ===========================================================================
// row_ptr: edges sorted by src; rowptr[i] = first index with src[e] >= i
// ===========================================================================
__global__ void build_rowptr_kernel(const int* __restrict__ src, int E) {
    int i = blockIdx.x * blockDim.x + threadIdx.x;
    if (i > NN) return;
    int lo = 0, hi = E;
    while (lo < hi) {
        int mid = (lo + hi) >> 1;
        if (src[mid] < i) lo = mid + 1; else hi = mid;
    }
    g_rowptr[i] = lo;
}

// ===========================================================================
// TF32 helpers (portable mma.sync PTX — compiles under compute_103)
// ===========================================================================
__device__ __forceinline__ uint32_t f2tf32(float x) {
    uint32_t r;
    asm("cvt.rna.tf32.f32 %0, %1;" : "=r"(r) : "f"(x));
    return r;
}

__device__ __forceinline__ void mma_tf32(float* c, const uint32_t* a, const uint32_t* b) {
    asm volatile(
        "mma.sync.aligned.m16n8k8.row.col.f32.tf32.tf32.f32 "
        "{%0,%1,%2,%3}, {%4,%5,%6,%7}, {%8,%9}, {%0,%1,%2,%3};"
        : "+f"(c[0]), "+f"(c[1]), "+f"(c[2]), "+f"(c[3])
        : "r"(a[0]), "r"(a[1]), "r"(a[2]), "r"(a[3]),
          "r"(b[0]), "r"(b[1]));
}

// ===========================================================================
// Projection GEMM via TF32x3 (R10-proven): out = A @ W + bias.
// CTA tile 64x128, 8 warps (4M x 2N), warp tile 16x64. grid (157, 4).
// Q,S -> fp32 g_qkvs; K,V -> fp16 g_kv rows [K 256B | V 256B].
// ===========================================================================
#define ASTRIDE 20
#define BSTRIDE 136

__global__ __launch_bounds__(256)
void gemm_tf32_kernel(const float* __restrict__ xin,
                      const float* __restrict__ Wq, const float* __restrict__ Wk,
                      const float* __restrict__ Wv, const float* __restrict__ Ws,
                      const float* __restrict__ bq, const float* __restrict__ bk,
                      const float* __restrict__ bv, const float* __restrict__ bs,
                      int layer, int use_gh) {
    __shared__ uint32_t sAh[64 * ASTRIDE];
    __shared__ uint32_t sAl[64 * ASTRIDE];
    __shared__ uint32_t sBh[16 * BSTRIDE];
    __shared__ uint32_t sBl[16 * BSTRIDE];

    const int tid  = threadIdx.x;
    const int wid  = tid >> 5;
    const int lane = tid & 31;
    const int g    = lane >> 2;    // 0..7
    const int tg   = lane & 3;     // 0..3
    const int warpM = wid & 3;     // 0..3 (16 rows each)
    const int warpN = wid >> 2;    // 0..1 (64 cols each)

    const int rowbase = blockIdx.x * 64;
    const int mtx = blockIdx.y;

    const float* A = use_gh ? g_h : xin;
    const float* W = (mtx == 0 ? Wq : mtx == 1 ? Wk : mtx == 2 ? Wv : Ws)
                     + (size_t)layer * DD * DD;
    const float* bias = (mtx == 0 ? bq : mtx == 1 ? bk : mtx == 2 ? bv : bs)
                        + layer * DD;

    float acc[8][4];
    #pragma unroll
    for (int ni = 0; ni < 8; ++ni)
        #pragma unroll
        for (int r = 0; r < 4; ++r) acc[ni][r] = 0.f;

    for (int k0 = 0; k0 < DD; k0 += 16) {
        // ---- stage A chunk 64x16 (1 float4 per thread) ----
        {
            int row = tid >> 2;
            int c4  = tid & 3;
            int m = rowbase + row;
            float4 v = make_float4(0.f, 0.f, 0.f, 0.f);
            if (m < NN) v = *(const float4*)&A[(size_t)m * DD + k0 + c4 * 4];
            uint4 h, l;
            h.x = f2tf32(v.x); l.x = f2tf32(v.x - __uint_as_float(h.x));
            h.y = f2tf32(v.y); l.y = f2tf32(v.y - __uint_as_float(h.y));
            h.z = f2tf32(v.z); l.z = f2tf32(v.z - __uint_as_float(h.z));
            h.w = f2tf32(v.w); l.w = f2tf32(v.w - __uint_as_float(h.w));
            *(uint4*)&sAh[row * ASTRIDE + c4 * 4] = h;
            *(uint4*)&sAl[row * ASTRIDE + c4 * 4] = l;
        }
        // ---- stage B chunk 16x128 (2 float4 per thread) ----
        #pragma unroll
        for (int r = 0; r < 2; ++r) {
            int f = tid + r * 256;
            int kr = f >> 5;
            int c4 = f & 31;
            float4 v = *(const float4*)&W[(size_t)(k0 + kr) * DD + c4 * 4];
            uint4 h, l;
            h.x = f2tf32(v.x); l.x = f2tf32(v.x - __uint_as_float(h.x));
            h.y = f2tf32(v.y); l.y = f2tf32(v.y - __uint_as_float(h.y));
            h.z = f2tf32(v.z); l.z = f2tf32(v.z - __uint_as_float(h.z));
            h.w = f2tf32(v.w); l.w = f2tf32(v.w - __uint_as_float(h.w));
            *(uint4*)&sBh[kr * BSTRIDE + c4 * 4] = h;
            *(uint4*)&sBl[kr * BSTRIDE + c4 * 4] = l;
        }
        __syncthreads();

        #pragma unroll
        for (int ks = 0; ks < 2; ++ks) {
            int ko = ks * 8;
            uint32_t ah[4], al[4];
            int r0 = (warpM * 16 + g) * ASTRIDE;
            ah[0] = sAh[r0 + ko + tg];
            ah[1] = sAh[r0 + 8 * ASTRIDE + ko + tg];
            ah[2] = sAh[r0 + ko + tg + 4];
            ah[3] = sAh[r0 + 8 * ASTRIDE + ko + tg + 4];
            al[0] = sAl[r0 + ko + tg];
            al[1] = sAl[r0 + 8 * ASTRIDE + ko + tg];
            al[2] = sAl[r0 + ko + tg + 4];
            al[3] = sAl[r0 + 8 * ASTRIDE + ko + tg + 4];
            #pragma unroll
            for (int ni = 0; ni < 8; ++ni) {
                int n0 = warpN * 64 + ni * 8 + g;
                uint32_t bh[2], bl[2];
                bh[0] = sBh[(ko + tg) * BSTRIDE + n0];
                bh[1] = sBh[(ko + tg + 4) * BSTRIDE + n0];
                bl[0] = sBl[(ko + tg) * BSTRIDE + n0];
                bl[1] = sBl[(ko + tg + 4) * BSTRIDE + n0];
                mma_tf32(acc[ni], ah, bh);
                mma_tf32(acc[ni], al, bh);
                mma_tf32(acc[ni], ah, bl);
            }
        }
        __syncthreads();
    }

    // ---- epilogue ----
    int m0 = rowbase + warpM * 16 + g;
    int m1 = m0 + 8;
    #pragma unroll
    for (int ni = 0; ni < 8; ++ni) {
        int n = warpN * 64 + ni * 8 + tg * 2;
        float2 b2 = *(const float2*)&bias[n];
        float2 o0 = make_float2(acc[ni][0] + b2.x, acc[ni][1] + b2.y);
        float2 o1 = make_float2(acc[ni][2] + b2.x, acc[ni][3] + b2.y);
        if (mtx == 0 || mtx == 3) {
            float* outb = g_qkvs + (mtx == 0 ? 0 : NDSZ);
            if (m0 < NN) *(float2*)&outb[(size_t)m0 * DD + n] = o0;
            if (m1 < NN) *(float2*)&outb[(size_t)m1 * DD + n] = o1;
        } else {
            // node row 512B: K fp16 dims at [0,256), V fp16 dims at [256,512)
            size_t sect = (size_t)(mtx == 2 ? 256 : 0) + (size_t)n * 2;
            if (m0 < NN)
                *(__half2*)((char*)g_kv + (size_t)m0 * 512 + sect) = __floats2half2_rn(o0.x, o0.y);
            if (m1 < NN)
                *(__half2*)((char*)g_kv + (size_t)m1 * 512 + sect) = __floats2half2_rn(o1.x, o1.y);
        }
    }
}

// ===========================================================================
// Attention: one warp per node; lane = (sub=lane>>3, head=lane&7).
// Warp processes 4 edges/iter; each lane handles one edge x one full head
// (16 dims) -> no per-edge shuffles; softmax ops issued once per 4 edges.
// 4 per-sub online-softmax streams, flash-merged across subs at the end.
// fp16 K/V storage, fp32 math.
// ===========================================================================
__global__ __launch_bounds__(256)
void attn_kernel(const float* __restrict__ xin,
                 const int* __restrict__ nbr,
                 float* __restrict__ outp, int mode) {
    int gwarp = (blockIdx.x * blockDim.x + threadIdx.x) >> 5;
    if (gwarp >= NN) return;
    const int lane = threadIdx.x & 31;
    const int sub  = lane >> 3;    // 0..3 edge slot
    const int head = lane & 7;     // 0..7
    const int i = gwarp;

    const float* Q  = g_qkvs;
    const float* Sp = g_qkvs + NDSZ;
    const float* h  = mode ? g_h : xin;

    // q head slice (16 floats), fold 1/sqrt(16)=0.25
    float q[16];
    {
        const float* qp = Q + (size_t)i * DD + head * 16;
        #pragma unroll
        for (int t = 0; t < 4; ++t) {
            float4 v = *(const float4*)(qp + 4 * t);
            q[4*t+0] = v.x * 0.25f; q[4*t+1] = v.y * 0.25f;
            q[4*t+2] = v.z * 0.25f; q[4*t+3] = v.w * 0.25f;
        }
    }

    float m = -1e30f, z = 0.f;
    float acc[16];
    #pragma unroll
    for (int t = 0; t < 16; ++t) acc[t] = 0.f;

    const int e0 = g_rowptr[i];
    const int e1 = g_rowptr[i + 1];

    for (int e = e0; e < e1; e += 4) {
        int ee = e + sub;
        bool valid = (ee < e1);
        if (!valid) ee = e1 - 1;
        int j = nbr[ee];
        const char* base = (const char*)g_kv + (size_t)j * 512 + head * 32;
        uint4 kk0 = *(const uint4*)(base);
        uint4 kk1 = *(const uint4*)(base + 16);
        uint4 vv0 = *(const uint4*)(base + 256);
        uint4 vv1 = *(const uint4*)(base + 272);

        // dot (fp32 math, fp16 inputs)
        float d = 0.f;
        {
            const __half2* kp0 = (const __half2*)&kk0;
            const __half2* kp1 = (const __half2*)&kk1;
            #pragma unroll
            for (int t = 0; t < 4; ++t) {
                float2 f = __half22float2(kp0[t]);
                d += q[2*t] * f.x + q[2*t+1] * f.y;
            }
            #pragma unroll
            for (int t = 0; t < 4; ++t) {
                float2 f = __half22float2(kp1[t]);
                d += q[8+2*t] * f.x + q[8+2*t+1] * f.y;
            }
        }

        float nm = valid ? fmaxf(m, d) : m;
        float sc = __expf(m - nm);           // 1 when nm==m
        float p  = valid ? __expf(d - nm) : 0.f;
        z = z * sc + p;
        {
            const __half2* vp0 = (const __half2*)&vv0;
            const __half2* vp1 = (const __half2*)&vv1;
            #pragma unroll
            for (int t = 0; t < 4; ++t) {
                float2 f = __half22float2(vp0[t]);
                acc[2*t]   = acc[2*t]   * sc + p * f.x;
                acc[2*t+1] = acc[2*t+1] * sc + p * f.y;
            }
            #pragma unroll
            for (int t = 0; t < 4; ++t) {
                float2 f = __half22float2(vp1[t]);
                acc[8+2*t]   = acc[8+2*t]   * sc + p * f.x;
                acc[8+2*t+1] = acc[8+2*t+1] * sc + p * f.y;
            }
        }
        m = nm;
    }

    // flash-merge the 4 sub streams (xor 8, then xor 16)
    #pragma unroll
    for (int off = 8; off <= 16; off <<= 1) {
        float om = __shfl_xor_sync(0xFFFFFFFFu, m, off);
        float oz = __shfl_xor_sync(0xFFFFFFFFu, z, off);
        float oacc[16];
        #pragma unroll
        for (int t = 0; t < 16; ++t)
            oacc[t] = __shfl_xor_sync(0xFFFFFFFFu, acc[t], off);
        float M = fmaxf(m, om);
        float c0 = __expf(m - M);
        float c1 = __expf(om - M);
        z = z * c0 + oz * c1;
        #pragma unroll
        for (int t = 0; t < 16; ++t) acc[t] = acc[t] * c0 + oacc[t] * c1;
        m = M;
    }

    if (sub == 0) {
        float inv = 1.f / z;
        const float* hp = h  + (size_t)i * DD + head * 16;
        const float* sp = Sp + (size_t)i * DD + head * 16;
        float* op = (mode == 0 ? g_h : outp) + (size_t)i * DD + head * 16;
        #pragma unroll
        for (int t = 0; t < 4; ++t) {
            float4 hv = *(const float4*)(hp + 4 * t);
            float4 sv = *(const float4*)(sp + 4 * t);
            float4 o;
            o.x = acc[4*t+0] * inv + hv.x + sv.x;
            o.y = acc[4*t+1] * inv + hv.y + sv.y;
            o.z = acc[4*t+2] * inv + hv.z + sv.z;
            o.w = acc[4*t+3] * inv + hv.w + sv.w;
            if (mode == 0) {
                o.x = fmaxf(o.x, 0.f); o.y = fmaxf(o.y, 0.f);
                o.z = fmaxf(o.z, 0.f); o.w = fmaxf(o.w, 0.f);
            }
            *(float4*)(op + 4 * t) = o;
        }
    }
}

// ===========================================================================
// Launch — only kernel launches.
// Inputs: 0=x 1=Wq 2=bq 3=Wk 4=bk 5=Wv 6=bv 7=Ws 8=bs 9=attn_window[2,E] int32
// ===========================================================================
extern "C" void kernel_launch(void* const* d_in, const int* in_sizes, int n_in,
                              void* d_out, int out_size) {
    const float* x  = (const float*)d_in[0];
    const float* Wq = (const float*)d_in[1];
    const float* bq = (const float*)d_in[2];
    const float* Wk = (const float*)d_in[3];
    const float* bk = (const float*)d_in[4];
    const float* Wv = (const float*)d_in[5];
    const float* bv = (const float*)d_in[6];
    const float* Ws = (const float*)d_in[7];
    const float* bs = (const float*)d_in[8];
    const int*   aw = (const int*)d_in[9];
    const int E = in_sizes[9] / 2;
    const int* src = aw;
    const int* dst = aw + E;

    build_rowptr_kernel<<<(NN + 256) / 256, 256>>>(src, E);

    dim3 ggrid((NN + 63) / 64, 4);
    dim3 agrid((NN * 32 + 255) / 256);

    // Layer 0
    gemm_tf32_kernel<<<ggrid, 256>>>(x, Wq, Wk, Wv, Ws, bq, bk, bv, bs, 0, 0);
    attn_kernel<<<agrid, 256>>>(x, dst, nullptr, 0);

    // Layer 1
    gemm_tf32_kernel<<<ggrid, 256>>>(x, Wq, Wk, Wv, Ws, bq, bk, bv, bs, 1, 1);
    attn_kernel<<<agrid, 256>>>(nullptr, dst, (float*)d_out, 1);
}

// round 14
// speedup vs baseline: 1.1501x; 1.0179x over previous
#include <cuda_runtime.h>
#include <cuda_bf16.h>
#include <cuda_fp16.h>
#include <cstdint>

// Problem constants
#define NN 10000
#define DD 128
#define NDSZ (NN * DD)

// Scratch (device globals; no allocations)
__device__ float g_qkvs[2 * NDSZ];        // Q (fp32), S (fp32)
__device__ uint4 g_kv[NN * 32];           // per node 512B: [K 128 fp16 | V 128 fp16]
__device__ float g_h[NDSZ];               // hidden after layer 0
__device__ int   g_rowptr[NN + 1];

// ===========================================================================
// row_ptr: edges sorted by src; rowptr[i] = first index with src[e] >= i
// ===========================================================================
__global__ void build_rowptr_kernel(const int* __restrict__ src, int E) {
    int i = blockIdx.x * blockDim.x + threadIdx.x;
    if (i > NN) return;
    int lo = 0, hi = E;
    while (lo < hi) {
        int mid = (lo + hi) >> 1;
        if (src[mid] < i) lo = mid + 1; else hi = mid;
    }
    g_rowptr[i] = lo;
}

// ===========================================================================
// TF32 helpers (portable mma.sync PTX — compiles under compute_103)
// ===========================================================================
__device__ __forceinline__ uint32_t f2tf32(float x) {
    uint32_t r;
    asm("cvt.rna.tf32.f32 %0, %1;" : "=r"(r) : "f"(x));
    return r;
}

__device__ __forceinline__ void mma_tf32(float* c, const uint32_t* a, const uint32_t* b) {
    asm volatile(
        "mma.sync.aligned.m16n8k8.row.col.f32.tf32.tf32.f32 "
        "{%0,%1,%2,%3}, {%4,%5,%6,%7}, {%8,%9}, {%0,%1,%2,%3};"
        : "+f"(c[0]), "+f"(c[1]), "+f"(c[2]), "+f"(c[3])
        : "r"(a[0]), "r"(a[1]), "r"(a[2]), "r"(a[3]),
          "r"(b[0]), "r"(b[1]));
}

// ===========================================================================
// Projection GEMM via TF32x3 with register-prefetch pipeline:
// chunk n+1's LDGs are issued before chunk n's MMA section, hiding global
// latency behind tensor work. CTA tile 64x128, 8 warps, warp tile 16x64.
// grid (157, 4). Q,S -> fp32 g_qkvs; K,V -> fp16 g_kv [K 256B | V 256B].
// ===========================================================================
#define ASTRIDE 20
#define BSTRIDE 136

__global__ __launch_bounds__(256, 3)
void gemm_tf32_kernel(const float* __restrict__ xin,
                      const float* __restrict__ Wq, const float* __restrict__ Wk,
                      const float* __restrict__ Wv, const float* __restrict__ Ws,
                      const float* __restrict__ bq, const float* __restrict__ bk,
                      const float* __restrict__ bv, const float* __restrict__ bs,
                      int layer, int use_gh) {
    __shared__ uint32_t sAh[64 * ASTRIDE];
    __shared__ uint32_t sAl[64 * ASTRIDE];
    __shared__ uint32_t sBh[16 * BSTRIDE];
    __shared__ uint32_t sBl[16 * BSTRIDE];

    const int tid  = threadIdx.x;
    const int wid  = tid >> 5;
    const int lane = tid & 31;
    const int g    = lane >> 2;    // 0..7
    const int tg   = lane & 3;     // 0..3
    const int warpM = wid & 3;     // 0..3 (16 rows each)
    const int warpN = wid >> 2;    // 0..1 (64 cols each)

    const int rowbase = blockIdx.x * 64;
    const int mtx = blockIdx.y;

    const float* A = use_gh ? g_h : xin;
    const float* W = (mtx == 0 ? Wq : mtx == 1 ? Wk : mtx == 2 ? Wv : Ws)
                     + (size_t)layer * DD * DD;
    const float* bias = (mtx == 0 ? bq : mtx == 1 ? bk : mtx == 2 ? bv : bs)
                        + layer * DD;

    // staging indices (fixed per thread)
    const int arow = tid >> 2;          // 0..63
    const int ac4  = tid & 3;           // k group of 4
    const int am   = rowbase + arow;
    const bool avalid = (am < NN);
    const int bkr0 = tid >> 5;          // 0..7   (r=0)
    const int bc40 = tid & 31;
    const int bkr1 = (tid + 256) >> 5;  // 8..15  (r=1)
    const int bc41 = bc40;

    float acc[8][4];
    #pragma unroll
    for (int ni = 0; ni < 8; ++ni)
        #pragma unroll
        for (int r = 0; r < 4; ++r) acc[ni][r] = 0.f;

    // preload chunk 0
    float4 pA = make_float4(0.f, 0.f, 0.f, 0.f);
    if (avalid) pA = *(const float4*)&A[(size_t)am * DD + 0 + ac4 * 4];
    float4 pB0 = *(const float4*)&W[(size_t)(0 + bkr0) * DD + bc40 * 4];
    float4 pB1 = *(const float4*)&W[(size_t)(0 + bkr1) * DD + bc41 * 4];

    #pragma unroll
    for (int kc = 0; kc < 8; ++kc) {
        // ---- convert + STS from held registers ----
        {
            uint4 h, l;
            h.x = f2tf32(pA.x); l.x = f2tf32(pA.x - __uint_as_float(h.x));
            h.y = f2tf32(pA.y); l.y = f2tf32(pA.y - __uint_as_float(h.y));
            h.z = f2tf32(pA.z); l.z = f2tf32(pA.z - __uint_as_float(h.z));
            h.w = f2tf32(pA.w); l.w = f2tf32(pA.w - __uint_as_float(h.w));
            *(uint4*)&sAh[arow * ASTRIDE + ac4 * 4] = h;
            *(uint4*)&sAl[arow * ASTRIDE + ac4 * 4] = l;
        }
        {
            uint4 h, l;
            h.x = f2tf32(pB0.x); l.x = f2tf32(pB0.x - __uint_as_float(h.x));
            h.y = f2tf32(pB0.y); l.y = f2tf32(pB0.y - __uint_as_float(h.y));
            h.z = f2tf32(pB0.z); l.z = f2tf32(pB0.z - __uint_as_float(h.z));
            h.w = f2tf32(pB0.w); l.w = f2tf32(pB0.w - __uint_as_float(h.w));
            *(uint4*)&sBh[bkr0 * BSTRIDE + bc40 * 4] = h;
            *(uint4*)&sBl[bkr0 * BSTRIDE + bc40 * 4] = l;
        }
        {
            uint4 h, l;
            h.x = f2tf32(pB1.x); l.x = f2tf32(pB1.x - __uint_as_float(h.x));
            h.y = f2tf32(pB1.y); l.y = f2tf32(pB1.y - __uint_as_float(h.y));
            h.z = f2tf32(pB1.z); l.z = f2tf32(pB1.z - __uint_as_float(h.z));
            h.w = f2tf32(pB1.w); l.w = f2tf32(pB1.w - __uint_as_float(h.w));
            *(uint4*)&sBh[bkr1 * BSTRIDE + bc41 * 4] = h;
            *(uint4*)&sBl[bkr1 * BSTRIDE + bc41 * 4] = l;
        }
        __syncthreads();

        // ---- prefetch next chunk (LDGs overlap with MMA below) ----
        if (kc < 7) {
            int k0 = (kc + 1) * 16;
            if (avalid) pA = *(const float4*)&A[(size_t)am * DD + k0 + ac4 * 4];
            pB0 = *(const float4*)&W[(size_t)(k0 + bkr0) * DD + bc40 * 4];
            pB1 = *(const float4*)&W[(size_t)(k0 + bkr1) * DD + bc41 * 4];
        }

        // ---- MMA section ----
        #pragma unroll
        for (int ks = 0; ks < 2; ++ks) {
            int ko = ks * 8;
            uint32_t ah[4], al[4];
            int r0 = (warpM * 16 + g) * ASTRIDE;
            ah[0] = sAh[r0 + ko + tg];
            ah[1] = sAh[r0 + 8 * ASTRIDE + ko + tg];
            ah[2] = sAh[r0 + ko + tg + 4];
            ah[3] = sAh[r0 + 8 * ASTRIDE + ko + tg + 4];
            al[0] = sAl[r0 + ko + tg];
            al[1] = sAl[r0 + 8 * ASTRIDE + ko + tg];
            al[2] = sAl[r0 + ko + tg + 4];
            al[3] = sAl[r0 + 8 * ASTRIDE + ko + tg + 4];
            #pragma unroll
            for (int ni = 0; ni < 8; ++ni) {
                int n0 = warpN * 64 + ni * 8 + g;
                uint32_t bh[2], bl[2];
                bh[0] = sBh[(ko + tg) * BSTRIDE + n0];
                bh[1] = sBh[(ko + tg + 4) * BSTRIDE + n0];
                bl[0] = sBl[(ko + tg) * BSTRIDE + n0];
                bl[1] = sBl[(ko + tg + 4) * BSTRIDE + n0];
                mma_tf32(acc[ni], ah, bh);
                mma_tf32(acc[ni], al, bh);
                mma_tf32(acc[ni], ah, bl);
            }
        }
        __syncthreads();
    }

    // ---- epilogue ----
    int m0 = rowbase + warpM * 16 + g;
    int m1 = m0 + 8;
    #pragma unroll
    for (int ni = 0; ni < 8; ++ni) {
        int n = warpN * 64 + ni * 8 + tg * 2;
        float2 b2 = *(const float2*)&bias[n];
        float2 o0 = make_float2(acc[ni][0] + b2.x, acc[ni][1] + b2.y);
        float2 o1 = make_float2(acc[ni][2] + b2.x, acc[ni][3] + b2.y);
        if (mtx == 0 || mtx == 3) {
            float* outb = g_qkvs + (mtx == 0 ? 0 : NDSZ);
            if (m0 < NN) *(float2*)&outb[(size_t)m0 * DD + n] = o0;
            if (m1 < NN) *(float2*)&outb[(size_t)m1 * DD + n] = o1;
        } else {
            // node row 512B: K fp16 dims at [0,256), V fp16 dims at [256,512)
            size_t sect = (size_t)(mtx == 2 ? 256 : 0) + (size_t)n * 2;
            if (m0 < NN)
                *(__half2*)((char*)g_kv + (size_t)m0 * 512 + sect) = __floats2half2_rn(o0.x, o0.y);
            if (m1 < NN)
                *(__half2*)((char*)g_kv + (size_t)m1 * 512 + sect) = __floats2half2_rn(o1.x, o1.y);
        }
    }
}

// ===========================================================================
// Attention (R13-proven): one warp per node; lane = (sub=lane>>3, head=lane&7).
// 4 edges/iter; per-lane full-head dot (no per-edge shuffles); softmax
// bookkeeping once per 4 edges; 4 streams flash-merged via shfl at the end.
// ===========================================================================
__global__ __launch_bounds__(256)
void attn_kernel(const float* __restrict__ xin,
                 const int* __restrict__ nbr,
                 float* __restrict__ outp, int mode) {
    int gwarp = (blockIdx.x * blockDim.x + threadIdx.x) >> 5;
    if (gwarp >= NN) return;
    const int lane = threadIdx.x & 31;
    const int sub  = lane >> 3;    // 0..3 edge slot
    const int head = lane & 7;     // 0..7
    const int i = gwarp;

    const float* Q  = g_qkvs;
    const float* Sp = g_qkvs + NDSZ;
    const float* h  = mode ? g_h : xin;

    // q head slice (16 floats), fold 1/sqrt(16)=0.25
    float q[16];
    {
        const float* qp = Q + (size_t)i * DD + head * 16;
        #pragma unroll
        for (int t = 0; t < 4; ++t) {
            float4 v = *(const float4*)(qp + 4 * t);
            q[4*t+0] = v.x * 0.25f; q[4*t+1] = v.y * 0.25f;
            q[4*t+2] = v.z * 0.25f; q[4*t+3] = v.w * 0.25f;
        }
    }

    float m = -1e30f, z = 0.f;
    float acc[16];
    #pragma unroll
    for (int t = 0; t < 16; ++t) acc[t] = 0.f;

    const int e0 = g_rowptr[i];
    const int e1 = g_rowptr[i + 1];

    for (int e = e0; e < e1; e += 4) {
        int ee = e + sub;
        bool valid = (ee < e1);
        if (!valid) ee = e1 - 1;
        int j = nbr[ee];
        const char* base = (const char*)g_kv + (size_t)j * 512 + head * 32;
        uint4 kk0 = *(const uint4*)(base);
        uint4 kk1 = *(const uint4*)(base + 16);
        uint4 vv0 = *(const uint4*)(base + 256);
        uint4 vv1 = *(const uint4*)(base + 272);

        // dot (fp32 math, fp16 inputs)
        float d = 0.f;
        {
            const __half2* kp0 = (const __half2*)&kk0;
            const __half2* kp1 = (const __half2*)&kk1;
            #pragma unroll
            for (int t = 0; t < 4; ++t) {
                float2 f = __half22float2(kp0[t]);
                d += q[2*t] * f.x + q[2*t+1] * f.y;
            }
            #pragma unroll
            for (int t = 0; t < 4; ++t) {
                float2 f = __half22float2(kp1[t]);
                d += q[8+2*t] * f.x + q[8+2*t+1] * f.y;
            }
        }

        float nm = valid ? fmaxf(m, d) : m;
        float sc = __expf(m - nm);           // 1 when nm==m
        float p  = valid ? __expf(d - nm) : 0.f;
        z = z * sc + p;
        {
            const __half2* vp0 = (const __half2*)&vv0;
            const __half2* vp1 = (const __half2*)&vv1;
            #pragma unroll
            for (int t = 0; t < 4; ++t) {
                float2 f = __half22float2(vp0[t]);
                acc[2*t]   = acc[2*t]   * sc + p * f.x;
                acc[2*t+1] = acc[2*t+1] * sc + p * f.y;
            }
            #pragma unroll
            for (int t = 0; t < 4; ++t) {
                float2 f = __half22float2(vp1[t]);
                acc[8+2*t]   = acc[8+2*t]   * sc + p * f.x;
                acc[8+2*t+1] = acc[8+2*t+1] * sc + p * f.y;
            }
        }
        m = nm;
    }

    // flash-merge the 4 sub streams (xor 8, then xor 16)
    #pragma unroll
    for (int off = 8; off <= 16; off <<= 1) {
        float om = __shfl_xor_sync(0xFFFFFFFFu, m, off);
        float oz = __shfl_xor_sync(0xFFFFFFFFu, z, off);
        float oacc[16];
        #pragma unroll
        for (int t = 0; t < 16; ++t)
            oacc[t] = __shfl_xor_sync(0xFFFFFFFFu, acc[t], off);
        float M = fmaxf(m, om);
        float c0 = __expf(m - M);
        float c1 = __expf(om - M);
        z = z * c0 + oz * c1;
        #pragma unroll
        for (int t = 0; t < 16; ++t) acc[t] = acc[t] * c0 + oacc[t] * c1;
        m = M;
    }

    if (sub == 0) {
        float inv = 1.f / z;
        const float* hp = h  + (size_t)i * DD + head * 16;
        const float* sp = Sp + (size_t)i * DD + head * 16;
        float* op = (mode == 0 ? g_h : outp) + (size_t)i * DD + head * 16;
        #pragma unroll
        for (int t = 0; t < 4; ++t) {
            float4 hv = *(const float4*)(hp + 4 * t);
            float4 sv = *(const float4*)(sp + 4 * t);
            float4 o;
            o.x = acc[4*t+0] * inv + hv.x + sv.x;
            o.y = acc[4*t+1] * inv + hv.y + sv.y;
            o.z = acc[4*t+2] * inv + hv.z + sv.z;
            o.w = acc[4*t+3] * inv + hv.w + sv.w;
            if (mode == 0) {
                o.x = fmaxf(o.x, 0.f); o.y = fmaxf(o.y, 0.f);
                o.z = fmaxf(o.z, 0.f); o.w = fmaxf(o.w, 0.f);
            }
            *(float4*)(op + 4 * t) = o;
        }
    }
}

// ===========================================================================
// Launch — only kernel launches.
// Inputs: 0=x 1=Wq 2=bq 3=Wk 4=bk 5=Wv 6=bv 7=Ws 8=bs 9=attn_window[2,E] int32
// ===========================================================================
extern "C" void kernel_launch(void* const* d_in, const int* in_sizes, int n_in,
                              void* d_out, int out_size) {
    const float* x  = (const float*)d_in[0];
    const float* Wq = (const float*)d_in[1];
    const float* bq = (const float*)d_in[2];
    const float* Wk = (const float*)d_in[3];
    const float* bk = (const float*)d_in[4];
    const float* Wv = (const float*)d_in[5];
    const float* bv = (const float*)d_in[6];
    const float* Ws = (const float*)d_in[7];
    const float* bs = (const float*)d_in[8];
    const int*   aw = (const int*)d_in[9];
    const int E = in_sizes[9] / 2;
    const int* src = aw;
    const int* dst = aw + E;

    build_rowptr_kernel<<<(NN + 256) / 256, 256>>>(src, E);

    dim3 ggrid((NN + 63) / 64, 4);
    dim3 agrid((NN * 32 + 255) / 256);

    // Layer 0
    gemm_tf32_kernel<<<ggrid, 256>>>(x, Wq, Wk, Wv, Ws, bq, bk, bv, bs, 0, 0);
    attn_kernel<<<agrid, 256>>>(x, dst, nullptr, 0);

    // Layer 1
    gemm_tf32_kernel<<<ggrid, 256>>>(x, Wq, Wk, Wv, Ws, bq, bk, bv, bs, 1, 1);
    attn_kernel<<<agrid, 256>>>(nullptr, dst, (float*)d_out, 1);
}